// round 6
// baseline (speedup 1.0000x reference)
#include <cuda_runtime.h>
#include <math.h>
#include <stdint.h>

// Problem constants
#define BB   4
#define LSEQ 4096
#define DD   1024
#define NLBL 8921
#define NLP  8960          // padded label count (multiple of 128/256)
#define NSEG 8
#define SEGL (LSEQ / NSEG) // 512

// GEMM tiling: CTA 128(M) x 256(N) x 32(K), warp tile 64x64 (2M x 4N warps)
#define Bb   128
#define BN   256
#define BK   32
#define STAGES 3
#define STG_FLOATS ((Bb + BN) * BK)           // 12288 floats = 48 KB/stage
#define SMEM_FLOATS (STAGES * STG_FLOATS)     // 36864 floats = 144 KB

// ---------------- scratch (device globals; no allocation allowed) ----------
__device__ float g_l1[(size_t)BB * LSEQ * DD];         // 64 MB
__device__ float g_scores[(size_t)BB * LSEQ * NLP];    // 587 MB
__device__ float g_xr [(size_t)BB * LSEQ * DD];        // 64 MB rounded x
__device__ float g_xt [(size_t)BB * DD * LSEQ];        // 64 MB rounded x^T
__device__ float g_w1r[(size_t)DD * DD];               // 4 MB
__device__ float g_w2r[(size_t)NLP * DD];              // 36.7 MB rounded+padded W2
__device__ float g_pmax[BB * NSEG * NLP];
__device__ float g_psum[BB * NSEG * NLP];
__device__ float g_max [BB * NLP];
__device__ float g_rsum[BB * NLP];

// ======================= helpers ===========================================
__device__ __forceinline__ uint32_t smem_u32(const void* p) {
    uint32_t a;
    asm("{ .reg .u64 t; cvta.to.shared.u64 t, %1; cvt.u32.u64 %0, t; }"
        : "=r"(a) : "l"(p));
    return a;
}
__device__ __forceinline__ float f_rna_tf32(float v) {
    uint32_t r;
    asm("cvt.rna.tf32.f32 %0, %1;" : "=r"(r) : "f"(v));
    return __uint_as_float(r);
}
__device__ __forceinline__ void cp_async16(uint32_t dst, const void* src) {
    asm volatile("cp.async.cg.shared.global [%0], [%1], 16;"
        :: "r"(dst), "l"(src));
}
#define CP_COMMIT() asm volatile("cp.async.commit_group;" ::: "memory")
#define CP_WAIT(n)  asm volatile("cp.async.wait_group %0;" :: "n"(n) : "memory")

__device__ __forceinline__ void mma_tf32(float* c, const uint32_t* a, const uint32_t* b) {
    asm volatile(
        "mma.sync.aligned.m16n8k8.row.col.f32.tf32.tf32.f32 "
        "{%0,%1,%2,%3}, {%4,%5,%6,%7}, {%8,%9}, {%0,%1,%2,%3};"
        : "+f"(c[0]), "+f"(c[1]), "+f"(c[2]), "+f"(c[3])
        : "r"(a[0]), "r"(a[1]), "r"(a[2]), "r"(a[3]),
          "r"(b[0]), "r"(b[1]));
}

// ldmatrix x4 of 8x8 b16 tiles == four (8 row x 4 col) b32 mma quadrants
__device__ __forceinline__ void ldsm4(uint32_t& r0, uint32_t& r1,
                                      uint32_t& r2, uint32_t& r3, uint32_t addr) {
    asm volatile("ldmatrix.sync.aligned.m8n8.x4.shared.b16 {%0,%1,%2,%3}, [%4];"
        : "=r"(r0), "=r"(r1), "=r"(r2), "=r"(r3) : "r"(addr));
}

// smem float offset for element (r, k) of a (rows x 32) tile; XOR swizzle keeps
// 16B chunks intact and makes all fragment reads bank-conflict-free.
__device__ __forceinline__ int swoff(int r, int k) {
    return (r << 5) + (k ^ ((r & 7) << 2));
}

// ---------------------------------------------------------------------------
// tf32 mma.sync GEMM (NT): C[M x Nc] = A[M x K] @ B[* x K]^T
// CTA tile 128x256, warp tile 64x64 (2M x 4N warps), BK=32, 3-stage cp.async.
// B rows padded to grid width (unguarded). A rows clamped if CLAMP_A.
// Output rows guarded to Mv if GUARD_M. blockIdx.z = batch via strides.
// ---------------------------------------------------------------------------
template <bool DO_TANH, bool GUARD_M, bool CLAMP_A>
__global__ __launch_bounds__(256, 1) void tc_gemm(
    const float* __restrict__ A, const float* __restrict__ Bm, float* __restrict__ C,
    int Mv, int Nc, int K, long sAb, long sBb, long sCb)
{
    extern __shared__ float smf[];
    const uint32_t sbase = smem_u32(smf);
    const int tid  = threadIdx.x;
    const int wid  = tid >> 5;
    const int lid  = tid & 31;
    const int g    = lid >> 2;
    const int tig  = lid & 3;
    const int wrow = wid & 1;    // 0..1 (M, 64 rows each)
    const int wcol = wid >> 1;   // 0..3 (N, 64 cols each)

    A  += (long)blockIdx.z * sAb;
    Bm += (long)blockIdx.z * sBb;
    C  += (long)blockIdx.z * sCb;

    const long row0 = (long)blockIdx.y * Bb;
    const long col0 = (long)blockIdx.x * BN;
    const int  nch  = K / BK;

    // tile-load mapping: threads cover 32 rows/pass, 8 float4 columns
    const int lr = tid >> 3;        // 0..31
    const int lc = tid & 7;         // float4 column

    // ldmatrix lane geometry (tile index = lid>>3)
    const int a_rin = ((lid >> 3) & 1) * 8 + (lid & 7);
    const int a_kg  = (lid >> 4) * 4;           // lanes 16-31 -> k+4
    const int b_rin = ((lid >> 4) & 1) * 8 + (lid & 7);
    const int b_kg  = ((lid >> 3) & 1) * 4;

    float acc[4][8][4];
    #pragma unroll
    for (int mt = 0; mt < 4; mt++)
        #pragma unroll
        for (int nt = 0; nt < 8; nt++)
            #pragma unroll
            for (int q = 0; q < 4; q++) acc[mt][nt][q] = 0.f;

    auto issue = [&](int i, int s) {
        const float* Ag = A + (long)i * BK;
        const float* Bg = Bm + col0 * K + (long)i * BK;
        uint32_t st = sbase + s * (STG_FLOATS * 4);
        #pragma unroll
        for (int t = 0; t < 4; t++) {          // A: 128 rows
            int r = lr + t * 32;
            long rA = row0 + r;
            if (CLAMP_A && rA > Mv - 1) rA = Mv - 1;
            cp_async16(st + swoff(r, lc * 4) * 4, Ag + rA * K + lc * 4);
        }
        uint32_t stB = st + Bb * BK * 4;
        #pragma unroll
        for (int t = 0; t < 8; t++) {          // B: 256 rows
            int r = lr + t * 32;
            cp_async16(stB + swoff(r, lc * 4) * 4, Bg + (long)r * K + lc * 4);
        }
    };

    #pragma unroll
    for (int i = 0; i < STAGES - 1; i++) { issue(i, i); CP_COMMIT(); }

    for (int i = 0; i < nch; i++) {
        CP_WAIT(STAGES - 2);
        __syncthreads();

        const int inext = i + STAGES - 1;
        if (inext < nch) issue(inext, inext % STAGES);
        CP_COMMIT();

        const uint32_t sAu = sbase + (i % STAGES) * (STG_FLOATS * 4);
        const uint32_t sBu = sAu + Bb * BK * 4;

        #pragma unroll
        for (int ks = 0; ks < 4; ks++) {
            const int kb = ks * 8;
            uint32_t af[4][4], bf[8][2];
            #pragma unroll
            for (int mt = 0; mt < 4; mt++) {
                int r = wrow * 64 + mt * 16 + a_rin;
                ldsm4(af[mt][0], af[mt][1], af[mt][2], af[mt][3],
                      sAu + 4u * swoff(r, kb + a_kg));
            }
            #pragma unroll
            for (int j = 0; j < 4; j++) {
                int r = wcol * 64 + j * 16 + b_rin;
                ldsm4(bf[2 * j][0], bf[2 * j][1], bf[2 * j + 1][0], bf[2 * j + 1][1],
                      sBu + 4u * swoff(r, kb + b_kg));
            }
            #pragma unroll
            for (int mt = 0; mt < 4; mt++)
                #pragma unroll
                for (int nt = 0; nt < 8; nt++)
                    mma_tf32(acc[mt][nt], af[mt], bf[nt]);
        }
    }

    // epilogue: float2 stores, rows g and g+8 per m-tile
    #pragma unroll
    for (int mt = 0; mt < 4; mt++) {
        long r0 = row0 + wrow * 64 + mt * 16 + g;
        long r1 = r0 + 8;
        bool ok0 = !GUARD_M || (r0 < Mv);
        bool ok1 = !GUARD_M || (r1 < Mv);
        #pragma unroll
        for (int nt = 0; nt < 8; nt++) {
            long cc = col0 + wcol * 64 + nt * 8 + 2 * tig;
            float2 v0 = make_float2(acc[mt][nt][0], acc[mt][nt][1]);
            float2 v1 = make_float2(acc[mt][nt][2], acc[mt][nt][3]);
            if (DO_TANH) {
                v0.x = f_rna_tf32(tanhf(v0.x)); v0.y = f_rna_tf32(tanhf(v0.y));
                v1.x = f_rna_tf32(tanhf(v1.x)); v1.y = f_rna_tf32(tanhf(v1.y));
            }
            if (ok0) *reinterpret_cast<float2*>(&C[r0 * Nc + cc]) = v0;
            if (ok1) *reinterpret_cast<float2*>(&C[r1 * Nc + cc]) = v1;
        }
    }
}

// ---------------------------------------------------------------------------
// pre-round helpers
// ---------------------------------------------------------------------------
__global__ void roundcpy(const float* __restrict__ src, float* __restrict__ dst, int n)
{
    int i = blockIdx.x * 256 + threadIdx.x;
    if (i < n) dst[i] = f_rna_tf32(src[i]);
}
__global__ void w2pad(const float* __restrict__ W2, float* __restrict__ dst)
{
    int i = blockIdx.x * 256 + threadIdx.x;
    if (i >= NLP * DD) return;
    int row = i / DD;
    dst[i] = (row < NLBL) ? f_rna_tf32(W2[i]) : 0.f;
}

// ---------------------------------------------------------------------------
// xprep: read x once; write xr = rna(x) (same layout) and xT = rna(x)^T
// ---------------------------------------------------------------------------
__global__ void xprep(const float* __restrict__ x, float* __restrict__ xr,
                      float* __restrict__ xT)
{
    __shared__ float tile[32][33];
    int b  = blockIdx.z;
    int d0 = blockIdx.x * 32;
    int l0 = blockIdx.y * 32;
    int tx = threadIdx.x, ty = threadIdx.y;  // 32 x 8
    #pragma unroll
    for (int i = 0; i < 4; i++) {
        size_t idx = ((size_t)b * LSEQ + l0 + ty + i * 8) * DD + d0 + tx;
        float v = f_rna_tf32(x[idx]);
        xr[idx] = v;
        tile[ty + i * 8][tx] = v;
    }
    __syncthreads();
    #pragma unroll
    for (int i = 0; i < 4; i++)
        xT[((size_t)b * DD + d0 + ty + i * 8) * LSEQ + l0 + tx] = tile[tx][ty + i * 8];
}

// ---------------------------------------------------------------------------
// Softmax over L of scores[B, L, NLP] (valid cols < NLBL), segmented.
// ---------------------------------------------------------------------------
__global__ void softmax_part(const float* __restrict__ scores)
{
    int n = blockIdx.x * 256 + threadIdx.x;
    int s = blockIdx.y;
    int b = blockIdx.z;
    float m = -1e30f, sum = 0.f;
    if (n < NLBL) {
        const float* p = scores + ((size_t)b * LSEQ + (size_t)s * SEGL) * NLP + n;
        #pragma unroll 4
        for (int l = 0; l < SEGL; l++) {
            float v = p[(size_t)l * NLP];
            if (v <= m) {
                sum += __expf(v - m);
            } else {
                sum = sum * __expf(m - v) + 1.f;
                m = v;
            }
        }
    }
    g_pmax[(b * NSEG + s) * NLP + n] = m;
    g_psum[(b * NSEG + s) * NLP + n] = sum;
}

__global__ void softmax_comb()
{
    int n = blockIdx.x * 256 + threadIdx.x;
    int b = blockIdx.z;
    float m = -1e30f;
    #pragma unroll
    for (int s = 0; s < NSEG; s++)
        m = fmaxf(m, g_pmax[(b * NSEG + s) * NLP + n]);
    float sum = 0.f;
    #pragma unroll
    for (int s = 0; s < NSEG; s++)
        sum += g_psum[(b * NSEG + s) * NLP + n] * __expf(g_pmax[(b * NSEG + s) * NLP + n] - m);
    g_max [b * NLP + n] = m;
    g_rsum[b * NLP + n] = 1.f / sum;
}

// ---------------------------------------------------------------------------
// attn[b,n,l] = rna_tf32(exp(scores[b,l,n]-max)*rsum)  (single rounded copy;
// feeds both the output comparison and GEMM3)
// ---------------------------------------------------------------------------
__global__ void attn_transpose(const float* __restrict__ scores, float* __restrict__ attn)
{
    __shared__ float tile[32][33];
    int b  = blockIdx.z;
    int n0 = blockIdx.x * 32;
    int l0 = blockIdx.y * 32;
    int tx = threadIdx.x, ty = threadIdx.y;  // 32 x 8

    int n = n0 + tx;
    float m = 0.f, r = 0.f;
    if (n < NLBL) {
        m = g_max [b * NLP + n];
        r = g_rsum[b * NLP + n];
    }
    #pragma unroll
    for (int i = 0; i < 4; i++) {
        int l = l0 + ty + i * 8;
        float v = 0.f;
        if (n < NLBL)
            v = __expf(scores[((size_t)b * LSEQ + l) * NLP + n] - m) * r;
        tile[ty + i * 8][tx] = v;
    }
    __syncthreads();
    #pragma unroll
    for (int i = 0; i < 4; i++) {
        int n2 = n0 + ty + i * 8;
        int l  = l0 + tx;
        if (n2 < NLBL)
            attn[((size_t)b * NLBL + n2) * LSEQ + l] = f_rna_tf32(tile[tx][ty + i * 8]);
    }
}

// ---------------------------------------------------------------------------
extern "C" void kernel_launch(void* const* d_in, const int* in_sizes, int n_in,
                              void* d_out, int out_size)
{
    const float* x  = (const float*)d_in[0];   // [B, L, D]
    const float* W1 = (const float*)d_in[1];   // [D, D]
    const float* W2 = (const float*)d_in[2];   // [NL, D]

    float* out  = (float*)d_out;                          // [B, NL, D]
    float* attn = out + (size_t)BB * NLBL * DD;           // [B, NL, L]

    float *l1, *scores, *xr, *xt, *w1r, *w2r;
    cudaGetSymbolAddress((void**)&l1, g_l1);
    cudaGetSymbolAddress((void**)&scores, g_scores);
    cudaGetSymbolAddress((void**)&xr, g_xr);
    cudaGetSymbolAddress((void**)&xt, g_xt);
    cudaGetSymbolAddress((void**)&w1r, g_w1r);
    cudaGetSymbolAddress((void**)&w2r, g_w2r);

    const int SMEMB = SMEM_FLOATS * 4;  // 144 KB
    cudaFuncSetAttribute(tc_gemm<true,  false, false>, cudaFuncAttributeMaxDynamicSharedMemorySize, SMEMB);
    cudaFuncSetAttribute(tc_gemm<false, false, false>, cudaFuncAttributeMaxDynamicSharedMemorySize, SMEMB);
    cudaFuncSetAttribute(tc_gemm<false, true,  true >, cudaFuncAttributeMaxDynamicSharedMemorySize, SMEMB);

    // 0) pre-round operands to tf32 values (RNA); xprep also builds x^T
    xprep<<<dim3(DD / 32, LSEQ / 32, BB), dim3(32, 8)>>>(x, xr, xt);
    roundcpy<<<(DD * DD + 255) / 256, 256>>>(W1, w1r, DD * DD);
    w2pad<<<(NLP * DD + 255) / 256, 256>>>(W2, w2r);

    // 1) l1 = rna(tanh(xr @ w1r^T)):  M=16384, N=1024, K=1024
    tc_gemm<true, false, false><<<dim3(DD / BN, (BB * LSEQ) / Bb, 1), 256, SMEMB>>>(
        xr, w1r, l1, BB * LSEQ, DD, DD, 0, 0, 0);

    // 2) scores = l1 @ w2r^T:  M=16384, Nc=NLP, K=1024
    tc_gemm<false, false, false><<<dim3(NLP / BN, (BB * LSEQ) / Bb, 1), 256, SMEMB>>>(
        l1, w2r, scores, BB * LSEQ, NLP, DD, 0, 0, 0);

    // 3) column softmax stats over L
    softmax_part<<<dim3(NLP / 256, NSEG, BB), 256>>>(scores);
    softmax_comb<<<dim3(NLP / 256, 1, BB), 256>>>();

    // 4) attn = rna(softmax(scores)^T)  (single rounded copy, is the output)
    attn_transpose<<<dim3(NLP / 32, LSEQ / 32, BB), dim3(32, 8)>>>(scores, attn);

    // 5) out[b] = attn[b] @ xt[b]^T:  M=8921 (rows clamped), N=1024, K=4096
    tc_gemm<false, true, true><<<dim3(DD / BN, NLP / Bb, BB), 256, SMEMB>>>(
        attn, xt, out, NLBL, DD, LSEQ,
        (long)NLBL * LSEQ, (long)DD * LSEQ, (long)NLBL * DD);
}

// round 7
// speedup vs baseline: 1.1271x; 1.1271x over previous
#include <cuda_runtime.h>
#include <math.h>
#include <stdint.h>

// Problem constants
#define BB   4
#define LSEQ 4096
#define DD   1024
#define NLBL 8921
#define NLP  8960          // padded label count (multiple of 128/256)
#define NSEG 8
#define SEGL (LSEQ / NSEG) // 512

// GEMM tiling: CTA 128(M) x 128(N) x 32(K), 4 warps, warp tile 64x64
#define Bb   128
#define BN   128
#define BK   32
#define NTHR 128
#define STAGES 3
#define STG_FLOATS ((Bb + BN) * BK)           // 8192 floats = 32 KB/stage
#define SMEM_FLOATS (STAGES * STG_FLOATS)     // 24576 floats = 96 KB

// ---------------- scratch (device globals; no allocation allowed) ----------
__device__ float g_l1[(size_t)BB * LSEQ * DD];         // 64 MB
__device__ float g_scores[(size_t)BB * LSEQ * NLP];    // 587 MB
__device__ float g_xr [(size_t)BB * LSEQ * DD];        // 64 MB rounded x
__device__ float g_xt [(size_t)BB * DD * LSEQ];        // 64 MB rounded x^T
__device__ float g_w1r[(size_t)DD * DD];               // 4 MB
__device__ float g_w2r[(size_t)NLP * DD];              // 36.7 MB rounded+padded W2
__device__ float g_pmax[BB * NSEG * NLP];
__device__ float g_psum[BB * NSEG * NLP];
__device__ float g_max [BB * NLP];
__device__ float g_rsum[BB * NLP];

// ======================= helpers ===========================================
__device__ __forceinline__ uint32_t smem_u32(const void* p) {
    uint32_t a;
    asm("{ .reg .u64 t; cvta.to.shared.u64 t, %1; cvt.u32.u64 %0, t; }"
        : "=r"(a) : "l"(p));
    return a;
}
__device__ __forceinline__ float f_rna_tf32(float v) {
    uint32_t r;
    asm("cvt.rna.tf32.f32 %0, %1;" : "=r"(r) : "f"(v));
    return __uint_as_float(r);
}
__device__ __forceinline__ void cp_async16(uint32_t dst, const void* src) {
    asm volatile("cp.async.cg.shared.global [%0], [%1], 16;"
        :: "r"(dst), "l"(src));
}
#define CP_COMMIT() asm volatile("cp.async.commit_group;" ::: "memory")
#define CP_WAIT(n)  asm volatile("cp.async.wait_group %0;" :: "n"(n) : "memory")

__device__ __forceinline__ void mma_tf32(float* c, const uint32_t* a, const uint32_t* b) {
    asm volatile(
        "mma.sync.aligned.m16n8k8.row.col.f32.tf32.tf32.f32 "
        "{%0,%1,%2,%3}, {%4,%5,%6,%7}, {%8,%9}, {%0,%1,%2,%3};"
        : "+f"(c[0]), "+f"(c[1]), "+f"(c[2]), "+f"(c[3])
        : "r"(a[0]), "r"(a[1]), "r"(a[2]), "r"(a[3]),
          "r"(b[0]), "r"(b[1]));
}

// ldmatrix x4 of 8x8 b16 tiles == four (8 row x 4 col) b32 mma quadrants
__device__ __forceinline__ void ldsm4(uint32_t& r0, uint32_t& r1,
                                      uint32_t& r2, uint32_t& r3, uint32_t addr) {
    asm volatile("ldmatrix.sync.aligned.m8n8.x4.shared.b16 {%0,%1,%2,%3}, [%4];"
        : "=r"(r0), "=r"(r1), "=r"(r2), "=r"(r3) : "r"(addr));
}

// smem float offset for element (r, k) of a (rows x 32) tile; XOR swizzle keeps
// 16B chunks intact and makes all fragment reads bank-conflict-free.
__device__ __forceinline__ int swoff(int r, int k) {
    return (r << 5) + (k ^ ((r & 7) << 2));
}

// ---------------------------------------------------------------------------
// tf32 mma.sync GEMM (NT): C[M x Nc] = A[M x K] @ B[* x K]^T
// CTA 128x128, 4 warps (2Mx2N), warp tile 64x64, BK=32, 3-stage cp.async,
// 2 CTAs/SM. B rows padded to grid width (unguarded). A rows clamped if
// CLAMP_A. Output rows guarded to Mv if GUARD_M. blockIdx.z = batch.
// ---------------------------------------------------------------------------
template <bool DO_TANH, bool GUARD_M, bool CLAMP_A>
__global__ __launch_bounds__(NTHR, 2) void tc_gemm(
    const float* __restrict__ A, const float* __restrict__ Bm, float* __restrict__ C,
    int Mv, int Nc, int K, long sAb, long sBb, long sCb)
{
    extern __shared__ float smf[];
    const uint32_t sbase = smem_u32(smf);
    const int tid  = threadIdx.x;
    const int wid  = tid >> 5;
    const int lid  = tid & 31;
    const int g    = lid >> 2;
    const int tig  = lid & 3;
    const int wrow = wid & 1;    // 0..1 (M, 64 rows each)
    const int wcol = wid >> 1;   // 0..1 (N, 64 cols each)

    A  += (long)blockIdx.z * sAb;
    Bm += (long)blockIdx.z * sBb;
    C  += (long)blockIdx.z * sCb;

    const long row0 = (long)blockIdx.y * Bb;
    const long col0 = (long)blockIdx.x * BN;
    const int  nch  = K / BK;

    // tile-load mapping: 128 threads cover 16 rows/pass, 8 float4 columns
    const int lr = tid >> 3;        // 0..15
    const int lc = tid & 7;         // float4 column

    // ldmatrix lane geometry (tile index = lid>>3)
    const int a_rin = ((lid >> 3) & 1) * 8 + (lid & 7);
    const int a_kg  = (lid >> 4) * 4;           // lanes 16-31 -> k+4
    const int b_rin = ((lid >> 4) & 1) * 8 + (lid & 7);
    const int b_kg  = ((lid >> 3) & 1) * 4;

    float acc[4][8][4];
    #pragma unroll
    for (int mt = 0; mt < 4; mt++)
        #pragma unroll
        for (int nt = 0; nt < 8; nt++)
            #pragma unroll
            for (int q = 0; q < 4; q++) acc[mt][nt][q] = 0.f;

    auto issue = [&](int i, int s) {
        const float* Ag = A + (long)i * BK;
        const float* Bg = Bm + col0 * K + (long)i * BK;
        uint32_t st = sbase + s * (STG_FLOATS * 4);
        #pragma unroll
        for (int t = 0; t < 8; t++) {          // A: 128 rows, 16/pass
            int r = lr + t * 16;
            long rA = row0 + r;
            if (CLAMP_A && rA > Mv - 1) rA = Mv - 1;
            cp_async16(st + swoff(r, lc * 4) * 4, Ag + rA * K + lc * 4);
        }
        uint32_t stB = st + Bb * BK * 4;
        #pragma unroll
        for (int t = 0; t < 8; t++) {          // B: 128 rows
            int r = lr + t * 16;
            cp_async16(stB + swoff(r, lc * 4) * 4, Bg + (long)r * K + lc * 4);
        }
    };

    #pragma unroll
    for (int i = 0; i < STAGES - 1; i++) { issue(i, i); CP_COMMIT(); }

    for (int i = 0; i < nch; i++) {
        CP_WAIT(STAGES - 2);
        __syncthreads();

        const int inext = i + STAGES - 1;
        if (inext < nch) issue(inext, inext % STAGES);
        CP_COMMIT();

        const uint32_t sAu = sbase + (i % STAGES) * (STG_FLOATS * 4);
        const uint32_t sBu = sAu + Bb * BK * 4;

        #pragma unroll
        for (int ks = 0; ks < 4; ks++) {
            const int kb = ks * 8;
            uint32_t af[4][4], bf[8][2];
            #pragma unroll
            for (int mt = 0; mt < 4; mt++) {
                int r = wrow * 64 + mt * 16 + a_rin;
                ldsm4(af[mt][0], af[mt][1], af[mt][2], af[mt][3],
                      sAu + 4u * swoff(r, kb + a_kg));
            }
            #pragma unroll
            for (int j = 0; j < 4; j++) {
                int r = wcol * 64 + j * 16 + b_rin;
                ldsm4(bf[2 * j][0], bf[2 * j][1], bf[2 * j + 1][0], bf[2 * j + 1][1],
                      sBu + 4u * swoff(r, kb + b_kg));
            }
            #pragma unroll
            for (int mt = 0; mt < 4; mt++)
                #pragma unroll
                for (int nt = 0; nt < 8; nt++)
                    mma_tf32(acc[mt][nt], af[mt], bf[nt]);
        }
    }

    // epilogue: float2 stores, rows g and g+8 per m-tile
    #pragma unroll
    for (int mt = 0; mt < 4; mt++) {
        long r0 = row0 + wrow * 64 + mt * 16 + g;
        long r1 = r0 + 8;
        bool ok0 = !GUARD_M || (r0 < Mv);
        bool ok1 = !GUARD_M || (r1 < Mv);
        #pragma unroll
        for (int nt = 0; nt < 8; nt++) {
            long cc = col0 + wcol * 64 + nt * 8 + 2 * tig;
            float2 v0 = make_float2(acc[mt][nt][0], acc[mt][nt][1]);
            float2 v1 = make_float2(acc[mt][nt][2], acc[mt][nt][3]);
            if (DO_TANH) {
                v0.x = f_rna_tf32(tanhf(v0.x)); v0.y = f_rna_tf32(tanhf(v0.y));
                v1.x = f_rna_tf32(tanhf(v1.x)); v1.y = f_rna_tf32(tanhf(v1.y));
            }
            if (ok0) *reinterpret_cast<float2*>(&C[r0 * Nc + cc]) = v0;
            if (ok1) *reinterpret_cast<float2*>(&C[r1 * Nc + cc]) = v1;
        }
    }
}

// ---------------------------------------------------------------------------
// pre-round helpers
// ---------------------------------------------------------------------------
__global__ void roundcpy(const float* __restrict__ src, float* __restrict__ dst, int n)
{
    int i = blockIdx.x * 256 + threadIdx.x;
    if (i < n) dst[i] = f_rna_tf32(src[i]);
}
__global__ void w2pad(const float* __restrict__ W2, float* __restrict__ dst)
{
    int i = blockIdx.x * 256 + threadIdx.x;
    if (i >= NLP * DD) return;
    int row = i / DD;
    dst[i] = (row < NLBL) ? f_rna_tf32(W2[i]) : 0.f;
}

// ---------------------------------------------------------------------------
// xprep: read x once; write xr = rna(x) (same layout) and xT = rna(x)^T
// ---------------------------------------------------------------------------
__global__ void xprep(const float* __restrict__ x, float* __restrict__ xr,
                      float* __restrict__ xT)
{
    __shared__ float tile[32][33];
    int b  = blockIdx.z;
    int d0 = blockIdx.x * 32;
    int l0 = blockIdx.y * 32;
    int tx = threadIdx.x, ty = threadIdx.y;  // 32 x 8
    #pragma unroll
    for (int i = 0; i < 4; i++) {
        size_t idx = ((size_t)b * LSEQ + l0 + ty + i * 8) * DD + d0 + tx;
        float v = f_rna_tf32(x[idx]);
        xr[idx] = v;
        tile[ty + i * 8][tx] = v;
    }
    __syncthreads();
    #pragma unroll
    for (int i = 0; i < 4; i++)
        xT[((size_t)b * DD + d0 + ty + i * 8) * LSEQ + l0 + tx] = tile[tx][ty + i * 8];
}

// ---------------------------------------------------------------------------
// Softmax over L of scores[B, L, NLP] (valid cols < NLBL), segmented.
// ---------------------------------------------------------------------------
__global__ void softmax_part(const float* __restrict__ scores)
{
    int n = blockIdx.x * 256 + threadIdx.x;
    int s = blockIdx.y;
    int b = blockIdx.z;
    float m = -1e30f, sum = 0.f;
    if (n < NLBL) {
        const float* p = scores + ((size_t)b * LSEQ + (size_t)s * SEGL) * NLP + n;
        #pragma unroll 4
        for (int l = 0; l < SEGL; l++) {
            float v = p[(size_t)l * NLP];
            if (v <= m) {
                sum += __expf(v - m);
            } else {
                sum = sum * __expf(m - v) + 1.f;
                m = v;
            }
        }
    }
    g_pmax[(b * NSEG + s) * NLP + n] = m;
    g_psum[(b * NSEG + s) * NLP + n] = sum;
}

__global__ void softmax_comb()
{
    int n = blockIdx.x * 256 + threadIdx.x;
    int b = blockIdx.z;
    float m = -1e30f;
    #pragma unroll
    for (int s = 0; s < NSEG; s++)
        m = fmaxf(m, g_pmax[(b * NSEG + s) * NLP + n]);
    float sum = 0.f;
    #pragma unroll
    for (int s = 0; s < NSEG; s++)
        sum += g_psum[(b * NSEG + s) * NLP + n] * __expf(g_pmax[(b * NSEG + s) * NLP + n] - m);
    g_max [b * NLP + n] = m;
    g_rsum[b * NLP + n] = 1.f / sum;
}

// ---------------------------------------------------------------------------
// attn[b,n,l] = rna_tf32(exp(scores[b,l,n]-max)*rsum)  (single rounded copy;
// feeds both the output comparison and GEMM3)
// ---------------------------------------------------------------------------
__global__ void attn_transpose(const float* __restrict__ scores, float* __restrict__ attn)
{
    __shared__ float tile[32][33];
    int b  = blockIdx.z;
    int n0 = blockIdx.x * 32;
    int l0 = blockIdx.y * 32;
    int tx = threadIdx.x, ty = threadIdx.y;  // 32 x 8

    int n = n0 + tx;
    float m = 0.f, r = 0.f;
    if (n < NLBL) {
        m = g_max [b * NLP + n];
        r = g_rsum[b * NLP + n];
    }
    #pragma unroll
    for (int i = 0; i < 4; i++) {
        int l = l0 + ty + i * 8;
        float v = 0.f;
        if (n < NLBL)
            v = __expf(scores[((size_t)b * LSEQ + l) * NLP + n] - m) * r;
        tile[ty + i * 8][tx] = v;
    }
    __syncthreads();
    #pragma unroll
    for (int i = 0; i < 4; i++) {
        int n2 = n0 + ty + i * 8;
        int l  = l0 + tx;
        if (n2 < NLBL)
            attn[((size_t)b * NLBL + n2) * LSEQ + l] = f_rna_tf32(tile[tx][ty + i * 8]);
    }
}

// ---------------------------------------------------------------------------
extern "C" void kernel_launch(void* const* d_in, const int* in_sizes, int n_in,
                              void* d_out, int out_size)
{
    const float* x  = (const float*)d_in[0];   // [B, L, D]
    const float* W1 = (const float*)d_in[1];   // [D, D]
    const float* W2 = (const float*)d_in[2];   // [NL, D]

    float* out  = (float*)d_out;                          // [B, NL, D]
    float* attn = out + (size_t)BB * NLBL * DD;           // [B, NL, L]

    float *l1, *scores, *xr, *xt, *w1r, *w2r;
    cudaGetSymbolAddress((void**)&l1, g_l1);
    cudaGetSymbolAddress((void**)&scores, g_scores);
    cudaGetSymbolAddress((void**)&xr, g_xr);
    cudaGetSymbolAddress((void**)&xt, g_xt);
    cudaGetSymbolAddress((void**)&w1r, g_w1r);
    cudaGetSymbolAddress((void**)&w2r, g_w2r);

    const int SMEMB = SMEM_FLOATS * 4;  // 96 KB
    cudaFuncSetAttribute(tc_gemm<true,  false, false>, cudaFuncAttributeMaxDynamicSharedMemorySize, SMEMB);
    cudaFuncSetAttribute(tc_gemm<false, false, false>, cudaFuncAttributeMaxDynamicSharedMemorySize, SMEMB);
    cudaFuncSetAttribute(tc_gemm<false, true,  true >, cudaFuncAttributeMaxDynamicSharedMemorySize, SMEMB);

    // 0) pre-round operands to tf32 values (RNA); xprep also builds x^T
    xprep<<<dim3(DD / 32, LSEQ / 32, BB), dim3(32, 8)>>>(x, xr, xt);
    roundcpy<<<(DD * DD + 255) / 256, 256>>>(W1, w1r, DD * DD);
    w2pad<<<(NLP * DD + 255) / 256, 256>>>(W2, w2r);

    // 1) l1 = rna(tanh(xr @ w1r^T)):  M=16384, N=1024, K=1024
    tc_gemm<true, false, false><<<dim3(DD / BN, (BB * LSEQ) / Bb, 1), NTHR, SMEMB>>>(
        xr, w1r, l1, BB * LSEQ, DD, DD, 0, 0, 0);

    // 2) scores = l1 @ w2r^T:  M=16384, Nc=NLP, K=1024
    tc_gemm<false, false, false><<<dim3(NLP / BN, (BB * LSEQ) / Bb, 1), NTHR, SMEMB>>>(
        l1, w2r, scores, BB * LSEQ, NLP, DD, 0, 0, 0);

    // 3) column softmax stats over L
    softmax_part<<<dim3(NLP / 256, NSEG, BB), 256>>>(scores);
    softmax_comb<<<dim3(NLP / 256, 1, BB), 256>>>();

    // 4) attn = rna(softmax(scores)^T)  (single rounded copy, is the output)
    attn_transpose<<<dim3(NLP / 32, LSEQ / 32, BB), dim3(32, 8)>>>(scores, attn);

    // 5) out[b] = attn[b] @ xt[b]^T:  M=8921 (rows clamped), N=1024, K=4096
    tc_gemm<false, true, true><<<dim3(DD / BN, NLP / Bb, BB), NTHR, SMEMB>>>(
        attn, xt, out, NLBL, DD, LSEQ,
        (long)NLBL * LSEQ, (long)DD * LSEQ, (long)NLBL * DD);
}

// round 8
// speedup vs baseline: 1.6419x; 1.4568x over previous
#include <cuda_runtime.h>
#include <cuda_fp16.h>
#include <math.h>
#include <stdint.h>

// Problem constants
#define BB   4
#define LSEQ 4096
#define DD   1024
#define NLBL 8921
#define NLP  8960          // padded label count (multiple of 128/256)
#define NSEG 8
#define SEGL (LSEQ / NSEG) // 512

// GEMM tiling: CTA 128(M) x 128(N) x 64(K halfs), 4 warps, warp tile 64x64
#define Bb   128
#define BN   128
#define BKH  64            // K elements per chunk (halfs), 128 B per row
#define NTHR 128
#define STAGES 3
#define TILE_BYTES (Bb * 128)                 // 16 KB per operand tile
#define STG_BYTES  (2 * TILE_BYTES)           // 32 KB per stage
#define SMEM_BYTES (STAGES * STG_BYTES)       // 96 KB

// ---------------- scratch (device globals; no allocation allowed) ----------
__device__ __half g_l1h[(size_t)BB * LSEQ * DD];       // 32 MB  (l1 in fp16)
__device__ float  g_scores[(size_t)BB * LSEQ * NLP];   // 587 MB
__device__ __half g_xh [(size_t)BB * LSEQ * DD];       // 32 MB  fp16 x
__device__ __half g_xth[(size_t)BB * DD * LSEQ];       // 32 MB  fp16 x^T
__device__ __half g_w1h[(size_t)DD * DD];              // 2 MB
__device__ __half g_w2h[(size_t)NLP * DD];             // 18 MB  padded W2
__device__ __half g_attnh[(size_t)BB * NLP * LSEQ];    // 293 MB fp16 attn
__device__ float g_pmax[BB * NSEG * NLP];
__device__ float g_psum[BB * NSEG * NLP];
__device__ float g_max [BB * NLP];
__device__ float g_rsum[BB * NLP];

// ======================= helpers ===========================================
__device__ __forceinline__ uint32_t smem_u32(const void* p) {
    uint32_t a;
    asm("{ .reg .u64 t; cvta.to.shared.u64 t, %1; cvt.u32.u64 %0, t; }"
        : "=r"(a) : "l"(p));
    return a;
}
__device__ __forceinline__ void cp_async16(uint32_t dst, const void* src) {
    asm volatile("cp.async.cg.shared.global [%0], [%1], 16;"
        :: "r"(dst), "l"(src));
}
#define CP_COMMIT() asm volatile("cp.async.commit_group;" ::: "memory")
#define CP_WAIT(n)  asm volatile("cp.async.wait_group %0;" :: "n"(n) : "memory")

__device__ __forceinline__ void mma_f16(float* c, const uint32_t* a, const uint32_t* b) {
    asm volatile(
        "mma.sync.aligned.m16n8k16.row.col.f32.f16.f16.f32 "
        "{%0,%1,%2,%3}, {%4,%5,%6,%7}, {%8,%9}, {%0,%1,%2,%3};"
        : "+f"(c[0]), "+f"(c[1]), "+f"(c[2]), "+f"(c[3])
        : "r"(a[0]), "r"(a[1]), "r"(a[2]), "r"(a[3]),
          "r"(b[0]), "r"(b[1]));
}

// ldmatrix x4 of 8x8 b16 tiles (fp16-native fragment loads)
__device__ __forceinline__ void ldsm4(uint32_t& r0, uint32_t& r1,
                                      uint32_t& r2, uint32_t& r3, uint32_t addr) {
    asm volatile("ldmatrix.sync.aligned.m8n8.x4.shared.b16 {%0,%1,%2,%3}, [%4];"
        : "=r"(r0), "=r"(r1), "=r"(r2), "=r"(r3) : "r"(addr));
}

// byte offset of 16B chunk c16 (0..7) in row r of a (rows x 128B) tile;
// XOR swizzle keeps cp.async 16B chunks intact, conflict-free ldmatrix.
__device__ __forceinline__ uint32_t swoffh(int r, int c16) {
    return ((uint32_t)r << 7) + (uint32_t)(((c16) ^ (r & 7)) << 4);
}

// ---------------------------------------------------------------------------
// fp16 mma.sync GEMM (NT): C[M x Nc] = A[M x K] @ B[* x K]^T, fp32 accum.
// CTA 128x128, 4 warps (2Mx2N), warp tile 64x64, BKH=64 halfs/chunk,
// 3-stage cp.async, 2 CTAs/SM. A rows clamped if CLAMP_A; output rows
// guarded to Mv if GUARD_M. CT = float or __half output.
// ---------------------------------------------------------------------------
template <typename CT, bool DO_TANH, bool GUARD_M, bool CLAMP_A>
__global__ __launch_bounds__(NTHR, 2) void tc_gemm(
    const __half* __restrict__ A, const __half* __restrict__ Bm, CT* __restrict__ C,
    int Mv, int Nc, int K, long sAb, long sBb, long sCb)
{
    extern __shared__ char smc[];
    const uint32_t sbase = smem_u32(smc);
    const int tid  = threadIdx.x;
    const int wid  = tid >> 5;
    const int lid  = tid & 31;
    const int g    = lid >> 2;
    const int tig  = lid & 3;
    const int wrow = wid & 1;    // 0..1 (M, 64 rows each)
    const int wcol = wid >> 1;   // 0..1 (N, 64 cols each)

    A  += (long)blockIdx.z * sAb;
    Bm += (long)blockIdx.z * sBb;
    C  += (long)blockIdx.z * sCb;

    const long row0 = (long)blockIdx.y * Bb;
    const long col0 = (long)blockIdx.x * BN;
    const int  nch  = K / BKH;

    // tile-load mapping: 128 threads, 16 rows/pass, 8 16B-chunks per row
    const int lr = tid >> 3;        // 0..15
    const int lc = tid & 7;         // 16B chunk column

    // ldmatrix lane geometry: lanes 0-7 rows r..r+7 (k grp 0), 8-15 rows +8,
    // 16-23 rows r..r+7 (k grp 1), 24-31 rows +8 (k grp 1)
    const int m_rin = ((lid >> 3) & 1) * 8 + (lid & 7);
    const int m_k16 = (lid >> 4);   // 0 or 1 (16B = 8 halfs)

    float acc[4][8][4];
    #pragma unroll
    for (int mt = 0; mt < 4; mt++)
        #pragma unroll
        for (int nt = 0; nt < 8; nt++)
            #pragma unroll
            for (int q = 0; q < 4; q++) acc[mt][nt][q] = 0.f;

    auto issue = [&](int i, int s) {
        const __half* Ag = A + (long)i * BKH;
        const __half* Bg = Bm + col0 * K + (long)i * BKH;
        uint32_t st = sbase + s * STG_BYTES;
        #pragma unroll
        for (int t = 0; t < 8; t++) {          // A: 128 rows, 16/pass
            int r = lr + t * 16;
            long rA = row0 + r;
            if (CLAMP_A && rA > Mv - 1) rA = Mv - 1;
            cp_async16(st + swoffh(r, lc), Ag + rA * K + lc * 8);
        }
        uint32_t stB = st + TILE_BYTES;
        #pragma unroll
        for (int t = 0; t < 8; t++) {          // B: 128 rows
            int r = lr + t * 16;
            cp_async16(stB + swoffh(r, lc), Bg + (long)r * K + lc * 8);
        }
    };

    #pragma unroll
    for (int i = 0; i < STAGES - 1; i++) { issue(i, i); CP_COMMIT(); }

    for (int i = 0; i < nch; i++) {
        CP_WAIT(STAGES - 2);
        __syncthreads();

        const int inext = i + STAGES - 1;
        if (inext < nch) issue(inext, inext % STAGES);
        CP_COMMIT();

        const uint32_t sAu = sbase + (i % STAGES) * STG_BYTES;
        const uint32_t sBu = sAu + TILE_BYTES;

        #pragma unroll
        for (int ks = 0; ks < 4; ks++) {       // 4 k-steps of 16 halfs
            const int kb16 = ks * 2;           // 16B-chunk base
            uint32_t af[4][4], bf[8][2];
            #pragma unroll
            for (int mt = 0; mt < 4; mt++) {
                int r = wrow * 64 + mt * 16 + m_rin;
                ldsm4(af[mt][0], af[mt][1], af[mt][2], af[mt][3],
                      sAu + swoffh(r, kb16 + m_k16));
            }
            #pragma unroll
            for (int j = 0; j < 4; j++) {
                int r = wcol * 64 + j * 16 + m_rin;
                ldsm4(bf[2 * j][0], bf[2 * j + 1][0], bf[2 * j][1], bf[2 * j + 1][1],
                      sBu + swoffh(r, kb16 + m_k16));
            }
            #pragma unroll
            for (int mt = 0; mt < 4; mt++)
                #pragma unroll
                for (int nt = 0; nt < 8; nt++)
                    mma_f16(acc[mt][nt], af[mt], bf[nt]);
        }
    }

    // epilogue: rows g and g+8 per m-tile; float2 (CT=float) or half2 stores
    #pragma unroll
    for (int mt = 0; mt < 4; mt++) {
        long r0 = row0 + wrow * 64 + mt * 16 + g;
        long r1 = r0 + 8;
        bool ok0 = !GUARD_M || (r0 < Mv);
        bool ok1 = !GUARD_M || (r1 < Mv);
        #pragma unroll
        for (int nt = 0; nt < 8; nt++) {
            long cc = col0 + wcol * 64 + nt * 8 + 2 * tig;
            float2 v0 = make_float2(acc[mt][nt][0], acc[mt][nt][1]);
            float2 v1 = make_float2(acc[mt][nt][2], acc[mt][nt][3]);
            if (DO_TANH) {
                v0.x = tanhf(v0.x); v0.y = tanhf(v0.y);
                v1.x = tanhf(v1.x); v1.y = tanhf(v1.y);
            }
            if (sizeof(CT) == 4) {
                if (ok0) *reinterpret_cast<float2*>((float*)&C[r0 * Nc + cc]) = v0;
                if (ok1) *reinterpret_cast<float2*>((float*)&C[r1 * Nc + cc]) = v1;
            } else {
                if (ok0) *reinterpret_cast<__half2*>((__half*)&C[r0 * Nc + cc]) =
                    __floats2half2_rn(v0.x, v0.y);
                if (ok1) *reinterpret_cast<__half2*>((__half*)&C[r1 * Nc + cc]) =
                    __floats2half2_rn(v1.x, v1.y);
            }
        }
    }
}

// ---------------------------------------------------------------------------
// conversion helpers
// ---------------------------------------------------------------------------
__global__ void tohalf(const float* __restrict__ src, __half* __restrict__ dst, int n)
{
    int i = blockIdx.x * 256 + threadIdx.x;
    if (i < n) dst[i] = __float2half(src[i]);
}
__global__ void w2pad(const float* __restrict__ W2, __half* __restrict__ dst)
{
    int i = blockIdx.x * 256 + threadIdx.x;
    if (i >= NLP * DD) return;
    int row = i / DD;
    dst[i] = (row < NLBL) ? __float2half(W2[i]) : __float2half(0.f);
}

// ---------------------------------------------------------------------------
// xprep: read x once; write xh = f16(x) (same layout) and xth = f16(x)^T
// ---------------------------------------------------------------------------
__global__ void xprep(const float* __restrict__ x, __half* __restrict__ xh,
                      __half* __restrict__ xT)
{
    __shared__ float tile[32][33];
    int b  = blockIdx.z;
    int d0 = blockIdx.x * 32;
    int l0 = blockIdx.y * 32;
    int tx = threadIdx.x, ty = threadIdx.y;  // 32 x 8
    #pragma unroll
    for (int i = 0; i < 4; i++) {
        size_t idx = ((size_t)b * LSEQ + l0 + ty + i * 8) * DD + d0 + tx;
        float v = x[idx];
        xh[idx] = __float2half(v);
        tile[ty + i * 8][tx] = v;
    }
    __syncthreads();
    #pragma unroll
    for (int i = 0; i < 4; i++)
        xT[((size_t)b * DD + d0 + ty + i * 8) * LSEQ + l0 + tx] =
            __float2half(tile[tx][ty + i * 8]);
}

// ---------------------------------------------------------------------------
// Softmax over L of scores[B, L, NLP] (valid cols < NLBL), segmented.
// ---------------------------------------------------------------------------
__global__ void softmax_part(const float* __restrict__ scores)
{
    int n = blockIdx.x * 256 + threadIdx.x;
    int s = blockIdx.y;
    int b = blockIdx.z;
    float m = -1e30f, sum = 0.f;
    if (n < NLBL) {
        const float* p = scores + ((size_t)b * LSEQ + (size_t)s * SEGL) * NLP + n;
        #pragma unroll 4
        for (int l = 0; l < SEGL; l++) {
            float v = p[(size_t)l * NLP];
            if (v <= m) {
                sum += __expf(v - m);
            } else {
                sum = sum * __expf(m - v) + 1.f;
                m = v;
            }
        }
    }
    g_pmax[(b * NSEG + s) * NLP + n] = m;
    g_psum[(b * NSEG + s) * NLP + n] = sum;
}

__global__ void softmax_comb()
{
    int n = blockIdx.x * 256 + threadIdx.x;
    int b = blockIdx.z;
    float m = -1e30f;
    #pragma unroll
    for (int s = 0; s < NSEG; s++)
        m = fmaxf(m, g_pmax[(b * NSEG + s) * NLP + n]);
    float sum = 0.f;
    #pragma unroll
    for (int s = 0; s < NSEG; s++)
        sum += g_psum[(b * NSEG + s) * NLP + n] * __expf(g_pmax[(b * NSEG + s) * NLP + n] - m);
    g_max [b * NLP + n] = m;
    g_rsum[b * NLP + n] = 1.f / sum;
}

// ---------------------------------------------------------------------------
// attn[b,n,l] = exp(scores[b,l,n]-max)*rsum (fp32, exact -> output) and
// attnh = f16(attn) (feeds GEMM3)
// ---------------------------------------------------------------------------
__global__ void attn_transpose(const float* __restrict__ scores,
                               float* __restrict__ attn, __half* __restrict__ attnh)
{
    __shared__ float tile[32][33];
    int b  = blockIdx.z;
    int n0 = blockIdx.x * 32;
    int l0 = blockIdx.y * 32;
    int tx = threadIdx.x, ty = threadIdx.y;  // 32 x 8

    int n = n0 + tx;
    float m = 0.f, r = 0.f;
    if (n < NLBL) {
        m = g_max [b * NLP + n];
        r = g_rsum[b * NLP + n];
    }
    #pragma unroll
    for (int i = 0; i < 4; i++) {
        int l = l0 + ty + i * 8;
        float v = 0.f;
        if (n < NLBL)
            v = __expf(scores[((size_t)b * LSEQ + l) * NLP + n] - m) * r;
        tile[ty + i * 8][tx] = v;
    }
    __syncthreads();
    #pragma unroll
    for (int i = 0; i < 4; i++) {
        int n2 = n0 + ty + i * 8;
        int l  = l0 + tx;
        if (n2 < NLBL) {
            float v = tile[tx][ty + i * 8];
            attn[((size_t)b * NLBL + n2) * LSEQ + l] = v;
            attnh[((size_t)b * NLP + n2) * LSEQ + l] = __float2half(v);
        }
    }
}

// ---------------------------------------------------------------------------
extern "C" void kernel_launch(void* const* d_in, const int* in_sizes, int n_in,
                              void* d_out, int out_size)
{
    const float* x  = (const float*)d_in[0];   // [B, L, D]
    const float* W1 = (const float*)d_in[1];   // [D, D]
    const float* W2 = (const float*)d_in[2];   // [NL, D]

    float* out  = (float*)d_out;                          // [B, NL, D]
    float* attn = out + (size_t)BB * NLBL * DD;           // [B, NL, L]

    __half *l1h, *xh, *xth, *w1h, *w2h, *attnh;
    float *scores;
    cudaGetSymbolAddress((void**)&l1h, g_l1h);
    cudaGetSymbolAddress((void**)&scores, g_scores);
    cudaGetSymbolAddress((void**)&xh, g_xh);
    cudaGetSymbolAddress((void**)&xth, g_xth);
    cudaGetSymbolAddress((void**)&w1h, g_w1h);
    cudaGetSymbolAddress((void**)&w2h, g_w2h);
    cudaGetSymbolAddress((void**)&attnh, g_attnh);

    cudaFuncSetAttribute(tc_gemm<__half, true,  false, false>,
                         cudaFuncAttributeMaxDynamicSharedMemorySize, SMEM_BYTES);
    cudaFuncSetAttribute(tc_gemm<float,  false, false, false>,
                         cudaFuncAttributeMaxDynamicSharedMemorySize, SMEM_BYTES);
    cudaFuncSetAttribute(tc_gemm<float,  false, true,  true >,
                         cudaFuncAttributeMaxDynamicSharedMemorySize, SMEM_BYTES);

    // 0) convert operands to fp16; xprep also builds x^T
    xprep<<<dim3(DD / 32, LSEQ / 32, BB), dim3(32, 8)>>>(x, xh, xth);
    tohalf<<<(DD * DD + 255) / 256, 256>>>(W1, w1h, DD * DD);
    w2pad<<<(NLP * DD + 255) / 256, 256>>>(W2, w2h);

    // 1) l1h = f16(tanh(xh @ w1h^T)):  M=16384, N=1024, K=1024
    tc_gemm<__half, true, false, false><<<dim3(DD / BN, (BB * LSEQ) / Bb, 1), NTHR, SMEM_BYTES>>>(
        xh, w1h, l1h, BB * LSEQ, DD, DD, 0, 0, 0);

    // 2) scores = l1h @ w2h^T (fp32 out):  M=16384, Nc=NLP, K=1024
    tc_gemm<float, false, false, false><<<dim3(NLP / BN, (BB * LSEQ) / Bb, 1), NTHR, SMEM_BYTES>>>(
        l1h, w2h, scores, BB * LSEQ, NLP, DD, 0, 0, 0);

    // 3) column softmax stats over L
    softmax_part<<<dim3(NLP / 256, NSEG, BB), 256>>>(scores);
    softmax_comb<<<dim3(NLP / 256, 1, BB), 256>>>();

    // 4) attn (exact fp32, output) + attnh (fp16 for GEMM3)
    attn_transpose<<<dim3(NLP / 32, LSEQ / 32, BB), dim3(32, 8)>>>(scores, attn, attnh);

    // 5) out[b] = attnh[b] @ xth[b]^T:  M=8921 (rows clamped), N=1024, K=4096
    tc_gemm<float, false, true, true><<<dim3(DD / BN, NLP / Bb, BB), NTHR, SMEM_BYTES>>>(
        attnh, xth, out, NLBL, DD, LSEQ,
        (long)NLP * LSEQ, (long)DD * LSEQ, (long)NLBL * DD);
}